// round 9
// baseline (speedup 1.0000x reference)
#include <cuda_runtime.h>
#include <cstdint>
#include <math.h>

#define NODE_DIM_   128
#define NUM_IRREPS_ 224
#define SPH_DIM_    480
#define HIDDEN_     576
#define NUM_BASIS_  20
#define N_NODES_    30000
#define N_EDGES_    480000
#define EPB_        8
#define MAXD_       32
#define SORT_BLKS_  148
#define MLP_BLKS_   296

// Scratch (device globals)
__device__ float g_hidden[(size_t)N_NODES_ * NODE_DIM_];
__device__ float g_scalar_out[(size_t)N_NODES_ * HIDDEN_];
__device__ int   g_count[N_NODES_];          // zero at load; re-zeroed each call
__device__ int   g_offs[N_NODES_ + 1];
__device__ int   g_cursor[N_NODES_];
__device__ int   g_perm[N_EDGES_];
__device__ unsigned int g_syncA;             // sort barrier counter (monotonic)
__device__ unsigned int g_syncB;             // mlp barrier counter (monotonic)
__device__ int   g_dummy;

// ---------------------------------------------------------------------------
// Grid-wide spin barrier for co-resident persistent grids.
// Monotonic counter: each barrier consumes exactly `nblk` arrivals, so it is
// reentrant across graph replays without any reset.
// ---------------------------------------------------------------------------
__device__ __forceinline__ void grid_barrier(unsigned int* ctr, int nblk) {
    __syncthreads();
    if (threadIdx.x == 0) {
        __threadfence();
        unsigned int arrive = atomicAdd(ctr, 1u) + 1u;
        unsigned int target = ((arrive - 1u) / (unsigned)nblk + 1u) * (unsigned)nblk;
        unsigned int v;
        do {
            asm volatile("ld.acquire.gpu.u32 %0, [%1];" : "=r"(v) : "l"(ctr));
        } while (v < target);
    }
    __syncthreads();
}

// ---------------------------------------------------------------------------
// Fused counting sort: histogram -> scan (block 0) -> permutation.
// ---------------------------------------------------------------------------
__global__ __launch_bounds__(1024) void sort_kernel(const int* __restrict__ edge_index) {
    const int gsz = gridDim.x * blockDim.x;
    const int gtid = blockIdx.x * blockDim.x + threadIdx.x;

    // phase A: histogram over dst
    for (int e = gtid; e < N_EDGES_; e += gsz)
        atomicAdd(&g_count[edge_index[e]], 1);
    grid_barrier(&g_syncA, SORT_BLKS_);

    // phase B: exclusive scan (block 0 only); zero g_count for next call
    if (blockIdx.x == 0) {
        __shared__ int s[1024];
        const int C = 30;                    // 1024*30 >= 30000
        const int t = threadIdx.x;
        const int base = t * C;
        int local[C];
        int sum = 0;
        #pragma unroll
        for (int j = 0; j < C; j++) {
            int i = base + j;
            int v = (i < N_NODES_) ? g_count[i] : 0;
            local[j] = sum;
            sum += v;
        }
        s[t] = sum;
        __syncthreads();
        #pragma unroll
        for (int d = 1; d < 1024; d <<= 1) {
            int x = (t >= d) ? s[t - d] : 0;
            __syncthreads();
            s[t] += x;
            __syncthreads();
        }
        int pre = (t > 0) ? s[t - 1] : 0;
        #pragma unroll
        for (int j = 0; j < C; j++) {
            int i = base + j;
            if (i < N_NODES_) {
                int o = pre + local[j];
                g_offs[i] = o;
                g_cursor[i] = o;
                g_count[i] = 0;
            }
        }
        if (t == 1023) g_offs[N_NODES_] = s[1023];
    }
    grid_barrier(&g_syncA, SORT_BLKS_);

    // phase C: permutation via atomic cursors
    for (int e = gtid; e < N_EDGES_; e += gsz) {
        int d = edge_index[e];
        int p = atomicAdd(&g_cursor[d], 1);
        g_perm[p] = e;
    }
}

// ---------------------------------------------------------------------------
// 64x64 tile GEMM body (4x4 microtile, contiguous fragments)
// ---------------------------------------------------------------------------
template <bool DO_SILU>
__device__ __forceinline__ void gemm_tile(
    const float* __restrict__ A, const float* __restrict__ B,
    const float* __restrict__ bias, float* __restrict__ C,
    int M, int N, int K, int bm, int bn,
    float (*As)[68], float (*Bs)[64]) {
    const int tid = threadIdx.x;
    const int tx = tid & 15;
    const int ty = tid >> 4;

    float acc[4][4] = {};

    for (int k0 = 0; k0 < K; k0 += 16) {
        #pragma unroll
        for (int i = 0; i < 4; i++) {
            int idx = tid + 256 * i;
            int m = idx >> 4, k = idx & 15;
            int gm = bm + m;
            As[k][m] = (gm < M) ? A[(size_t)gm * K + k0 + k] : 0.0f;
        }
        #pragma unroll
        for (int i = 0; i < 4; i++) {
            int idx = tid + 256 * i;
            int k = idx >> 6, n = idx & 63;
            Bs[k][n] = B[(size_t)(k0 + k) * N + bn + n];
        }
        __syncthreads();
        #pragma unroll
        for (int k = 0; k < 16; k++) {
            float4 aq = *reinterpret_cast<const float4*>(&As[k][ty * 4]);
            float4 bq = *reinterpret_cast<const float4*>(&Bs[k][tx * 4]);
            float a[4] = {aq.x, aq.y, aq.z, aq.w};
            float b[4] = {bq.x, bq.y, bq.z, bq.w};
            #pragma unroll
            for (int i = 0; i < 4; i++)
                #pragma unroll
                for (int j = 0; j < 4; j++)
                    acc[i][j] = fmaf(a[i], b[j], acc[i][j]);
        }
        __syncthreads();
    }

    float4 bq = *reinterpret_cast<const float4*>(&bias[bn + tx * 4]);
    float bv[4] = {bq.x, bq.y, bq.z, bq.w};
    #pragma unroll
    for (int i = 0; i < 4; i++) {
        int m = bm + ty * 4 + i;
        if (m >= M) continue;
        float4 o;
        float* op = &o.x;
        #pragma unroll
        for (int j = 0; j < 4; j++) {
            float v = acc[i][j] + bv[j];
            if (DO_SILU) v = v / (1.0f + expf(-v));
            op[j] = v;
        }
        *reinterpret_cast<float4*>(&C[(size_t)m * N + bn + tx * 4]) = o;
    }
}

// ---------------------------------------------------------------------------
// Fused node MLP: hidden = silu(x@W1+b1); scalar_out = hidden@W2+b2.
// Persistent grid with internal barrier between the two GEMMs.
// ---------------------------------------------------------------------------
__global__ __launch_bounds__(256) void mlp_kernel(
    const float* __restrict__ x_scalar,
    const float* __restrict__ W1, const float* __restrict__ b1,
    const float* __restrict__ W2, const float* __restrict__ b2) {
    __shared__ __align__(16) float As[16][68];
    __shared__ __align__(16) float Bs[16][64];

    const int MT = (N_NODES_ + 63) / 64;     // 469 row tiles

    // gemm1: [30000,128] = silu(x @ W1 + b1)
    for (int tile = blockIdx.x; tile < MT * 2; tile += gridDim.x) {
        int bm = (tile >> 1) * 64;
        int bn = (tile & 1) * 64;
        gemm_tile<true>(x_scalar, W1, b1, g_hidden,
                        N_NODES_, NODE_DIM_, NODE_DIM_, bm, bn, As, Bs);
    }
    grid_barrier(&g_syncB, MLP_BLKS_);
    // gemm2: [30000,576] = hidden @ W2 + b2
    for (int tile = blockIdx.x; tile < MT * 9; tile += gridDim.x) {
        int bm = (tile / 9) * 64;
        int bn = (tile % 9) * 64;
        gemm_tile<false>(g_hidden, W2, b2, g_scalar_out,
                         N_NODES_, HIDDEN_, NODE_DIM_, bm, bn, As, Bs);
    }
}

// ---------------------------------------------------------------------------
__global__ void dummy_kernel() { g_dummy = 0; }

// ---------------------------------------------------------------------------
// Persistent node kernel; thread t owns filter column t (scalar weights).
// rsh gather (the guaranteed-DRAM stream) is prefetched one batch ahead.
// ---------------------------------------------------------------------------
__device__ __forceinline__ int irrep_of(int k) {
    if (k < 128) return k;
    if (k < 320) return 128 + (k - 128) / 3;
    return 192 + (k - 320) / 5;
}

__global__ __launch_bounds__(576, 1) void node_kernel(
    const float* __restrict__ rbf, const float* __restrict__ fcut,
    const float* __restrict__ rsh, const int* __restrict__ edge_index,
    const float* __restrict__ Wrbf, const float* __restrict__ brbf,
    const float* __restrict__ x_scalar, const float* __restrict__ x_sph,
    float* __restrict__ out_scalar, float* __restrict__ out_sph) {
    const float* __restrict__ scalar_out = g_scalar_out;

    __shared__ __align__(16) float rbf_s[MAXD_][24];   // padded rows
    __shared__ int   eid_s[MAXD_];
    __shared__ int   src_s[MAXD_];
    __shared__ float fc_s[MAXD_];
    __shared__ float gate_s[2][EPB_][2 * NUM_IRREPS_];

    const int t = threadIdx.x;

    float w[NUM_BASIS_];
    #pragma unroll
    for (int k = 0; k < NUM_BASIS_; k++) w[k] = Wrbf[k * HIDDEN_ + t];
    const float bb = brbf[t];
    const int ir = (t < SPH_DIM_) ? irrep_of(t) : 0;
    const bool is_sph = (t < SPH_DIM_);

    int pp = 0;

    for (int n = blockIdx.x; n < N_NODES_; n += gridDim.x) {
        const int off = g_offs[n];
        const int deg = g_offs[n + 1] - off;

        float acc_sph = 0.0f;
        float acc_sc  = 0.0f;

        for (int c0 = 0; c0 < deg; c0 += MAXD_) {
            const int cnt = min(MAXD_, deg - c0);

            // ---- chunk metadata (pad with edge j=0, fc=0) ----
            if (t < MAXD_) {
                int j = (t < cnt) ? t : 0;
                int eid = __ldg(&g_perm[off + c0 + j]);
                eid_s[t] = eid;
                src_s[t] = __ldg(&edge_index[N_EDGES_ + eid]);
                fc_s[t]  = (t < cnt) ? __ldg(&fcut[eid]) : 0.0f;
            }
            for (int i = t; i < cnt * NUM_BASIS_; i += 576) {
                int e = i / NUM_BASIS_, k = i % NUM_BASIS_;
                int eid = __ldg(&g_perm[off + c0 + e]);     // L1 broadcast
                rbf_s[e][k] = __ldg(&rbf[(size_t)eid * NUM_BASIS_ + k]);
            }
            __syncthreads();

            const int nb = (cnt + EPB_ - 1) / EPB_;   // 1..4

            // prefetch batch 0's rsh (DRAM stream) immediately
            float rvP[EPB_];
            if (is_sph) {
                #pragma unroll
                for (int e = 0; e < EPB_; e++)
                    rvP[e] = __ldcs(&rsh[(size_t)eid_s[e] * SPH_DIM_ + t]);
            }

            for (int b = 0; b < nb; b++) {
                const int base = b * EPB_;

                // this batch's gathers
                float s[EPB_];
                #pragma unroll
                for (int e = 0; e < EPB_; e++)
                    s[e] = __ldg(&scalar_out[(size_t)src_s[base + e] * HIDDEN_ + t]);

                float xv[EPB_], rv[EPB_];
                if (is_sph) {
                    #pragma unroll
                    for (int e = 0; e < EPB_; e++) {
                        xv[e] = __ldg(&x_sph[(size_t)src_s[base + e] * SPH_DIM_ + t]);
                        rv[e] = rvP[e];
                    }
                    // prefetch next batch's rsh one full batch ahead
                    if (b + 1 < nb) {
                        #pragma unroll
                        for (int e = 0; e < EPB_; e++)
                            rvP[e] = __ldcs(
                                &rsh[(size_t)eid_s[base + EPB_ + e] * SPH_DIM_ + t]);
                    }
                }

                // filter dots: rbf via float4 broadcast LDS
                float a[EPB_];
                #pragma unroll
                for (int e = 0; e < EPB_; e++) {
                    const float4* rp =
                        reinterpret_cast<const float4*>(&rbf_s[base + e][0]);
                    float4 q0 = rp[0], q1 = rp[1], q2 = rp[2], q3 = rp[3], q4 = rp[4];
                    float v = bb;
                    v = fmaf(q0.x, w[0],  v); v = fmaf(q0.y, w[1],  v);
                    v = fmaf(q0.z, w[2],  v); v = fmaf(q0.w, w[3],  v);
                    v = fmaf(q1.x, w[4],  v); v = fmaf(q1.y, w[5],  v);
                    v = fmaf(q1.z, w[6],  v); v = fmaf(q1.w, w[7],  v);
                    v = fmaf(q2.x, w[8],  v); v = fmaf(q2.y, w[9],  v);
                    v = fmaf(q2.z, w[10], v); v = fmaf(q2.w, w[11], v);
                    v = fmaf(q3.x, w[12], v); v = fmaf(q3.y, w[13], v);
                    v = fmaf(q3.z, w[14], v); v = fmaf(q3.w, w[15], v);
                    v = fmaf(q4.x, w[16], v); v = fmaf(q4.y, w[17], v);
                    v = fmaf(q4.z, w[18], v); v = fmaf(q4.w, w[19], v);
                    a[e] = v;
                }

                #pragma unroll
                for (int e = 0; e < EPB_; e++)
                    s[e] = s[e] * (a[e] * fc_s[base + e]);

                if (t < 2 * NUM_IRREPS_) {
                    #pragma unroll
                    for (int e = 0; e < EPB_; e++) gate_s[pp][e][t] = s[e];
                } else {
                    #pragma unroll
                    for (int e = 0; e < EPB_; e++) acc_sc += s[e];
                }
                __syncthreads();

                if (is_sph) {
                    #pragma unroll
                    for (int e = 0; e < EPB_; e++) {
                        acc_sph = fmaf(xv[e], gate_s[pp][e][ir], acc_sph);
                        acc_sph = fmaf(rv[e], gate_s[pp][e][NUM_IRREPS_ + ir],
                                       acc_sph);
                    }
                }
                pp ^= 1;
            }
        }

        // residual + single write (covers deg==0 too)
        if (is_sph)
            out_sph[(size_t)n * SPH_DIM_ + t] =
                x_sph[(size_t)n * SPH_DIM_ + t] + acc_sph;
        if (t >= 2 * NUM_IRREPS_) {
            int c = t - 2 * NUM_IRREPS_;
            out_scalar[(size_t)n * NODE_DIM_ + c] =
                x_scalar[(size_t)n * NODE_DIM_ + c] + acc_sc;
        }
    }
}

// ---------------------------------------------------------------------------
extern "C" void kernel_launch(void* const* d_in, const int* in_sizes, int n_in,
                              void* d_out, int out_size) {
    const float* x_scalar = (const float*)d_in[0];
    const float* x_sph    = (const float*)d_in[1];
    const float* rbf      = (const float*)d_in[2];
    const float* fcut     = (const float*)d_in[3];
    const float* rsh      = (const float*)d_in[4];
    const int*   eidx     = (const int*)d_in[5];
    const float* W1       = (const float*)d_in[6];
    const float* b1       = (const float*)d_in[7];
    const float* W2       = (const float*)d_in[8];
    const float* b2       = (const float*)d_in[9];
    const float* Wrbf     = (const float*)d_in[10];
    const float* brbf     = (const float*)d_in[11];

    float* out        = (float*)d_out;
    float* out_scalar = out;
    float* out_sph    = out + (size_t)N_NODES_ * NODE_DIM_;

    sort_kernel<<<SORT_BLKS_, 1024>>>(eidx);                      // 0
    mlp_kernel<<<MLP_BLKS_, 256>>>(x_scalar, W1, b1, W2, b2);     // 1
    dummy_kernel<<<1, 32>>>();                                    // 2
    node_kernel<<<148, 576>>>(rbf, fcut, rsh, eidx, Wrbf, brbf,   // 3 (profiled)
                              x_scalar, x_sph, out_scalar, out_sph);
}